// round 8
// baseline (speedup 1.0000x reference)
#include <cuda_runtime.h>
#include <cuda_fp16.h>
#include <cstdint>

// ---------------------------------------------------------------------------
// out[64,8192] = x[64,8192] @ dequant(B[1024,8192] int4-packed, s[64,8192])
// HMMA fp16 GEMM, fp32 accum. NTILE=32, 256 threads/CTA, 2 CTAs/SM.
// 4-stage cp.async ring (A) + 4-slot register prefetch dequant (B).
// 8 warps: 2 output tiles (32x32) x 4-way k-split.
// ---------------------------------------------------------------------------

#define MDIM 64
#define KDIM 8192
#define NDIM 8192
#define NTILE 32
#define KTILE 64
#define NIT (KDIM / KTILE)   // 128 k-iterations
#define ASTRIDE 144          // smem row stride (64 fp16 + 16B pad)
#define NST 4
#define A_STG (64 * ASTRIDE)             // 9216
#define W_STG (32 * ASTRIDE)             // 4608
#define STG_BYTES (A_STG + W_STG)        // 13824
#define SMEM_TOTAL (NST * STG_BYTES)     // 55296 -> 2 CTAs/SM

// fp16 x, pre-permuted: slot j of each 8-wide group holds x[8w + perm[j]],
// perm = {0,4,1,5,2,6,3,7} (the LOP3 magic-dequant output order).
__device__ __align__(16) __half g_xh[MDIM * KDIM];

// ---------------------------- helpers ---------------------------------------
__device__ __forceinline__ uint32_t smem_u32(const void* p) {
    uint32_t a;
    asm("{ .reg .u64 t; cvta.to.shared.u64 t, %1; cvt.u32.u64 %0, t; }"
        : "=r"(a) : "l"(p));
    return a;
}

union HU { uint32_t u; __half2 h; };
__device__ __forceinline__ __half2 u2h(uint32_t u) { HU c; c.u = u; return c.h; }
__device__ __forceinline__ uint32_t h2u(__half2 h) { HU c; c.h = h; return c.u; }

// magic dequant: 8 int4 nibbles -> 8 fp16 * scale, k-order {0,4,1,5,2,6,3,7}
__device__ __forceinline__ uint4 dq8(uint32_t w, __half2 s2) {
    const __half2 c1032 = __half2half2(__ushort_as_half((unsigned short)0x6408)); // 1032.0
    uint4 o;
    o.x = h2u(__hmul2(__hsub2(u2h((w         & 0x000F000Fu) | 0x64006400u), c1032), s2));
    o.y = h2u(__hmul2(__hsub2(u2h(((w >> 4)  & 0x000F000Fu) | 0x64006400u), c1032), s2));
    o.z = h2u(__hmul2(__hsub2(u2h(((w >> 8)  & 0x000F000Fu) | 0x64006400u), c1032), s2));
    o.w = h2u(__hmul2(__hsub2(u2h(((w >> 12) & 0x000F000Fu) | 0x64006400u), c1032), s2));
    return o;
}

#define LDSM4(r, addr)                                                          \
    asm volatile("ldmatrix.sync.aligned.m8n8.x4.shared.b16 {%0,%1,%2,%3}, [%4];"\
        : "=r"((r)[0]), "=r"((r)[1]), "=r"((r)[2]), "=r"((r)[3]) : "r"(addr))

#define MMA16816(c, a, bb0, bb1)                                                \
    asm volatile("mma.sync.aligned.m16n8k16.row.col.f32.f16.f16.f32 "           \
        "{%0,%1,%2,%3},{%4,%5,%6,%7},{%8,%9},{%0,%1,%2,%3};"                    \
        : "+f"((c)[0]), "+f"((c)[1]), "+f"((c)[2]), "+f"((c)[3])                \
        : "r"((a)[0]), "r"((a)[1]), "r"((a)[2]), "r"((a)[3]), "r"(bb0), "r"(bb1))

#define CP_ASYNC16(dst, src) \
    asm volatile("cp.async.cg.shared.global [%0], [%1], 16;" :: "r"(dst), "l"(src))
#define CP_COMMIT() asm volatile("cp.async.commit_group;" ::: "memory")
#define CP_WAIT2()  asm volatile("cp.async.wait_group 2;" ::: "memory")

// ------------------------------- prep: x -> fp16 permuted --------------------
__global__ void prep_kernel(const float* __restrict__ x) {
    int i = blockIdx.x * 256 + threadIdx.x;
    if (i < MDIM * KDIM) {
        int j = i & 7;
        int p = (0x73625140u >> (j * 4)) & 0xF;   // perm {0,4,1,5,2,6,3,7}
        g_xh[i] = __float2half_rn(x[(i & ~7) | p]);
    }
}

// ------------------------------- main kernel --------------------------------
__global__ void __launch_bounds__(256, 2)
machete_kernel(const int* __restrict__ gB, const float* __restrict__ gs,
               float* __restrict__ out) {
    extern __shared__ __align__(16) unsigned char dsm[];
    const uint32_t sb0 = smem_u32(dsm);

    const int t = threadIdx.x;
    const int lane = t & 31;
    const int wid = t >> 5;
    const int n0 = blockIdx.x * NTILE;

    // ---------------- load-phase mapping (all 256 threads) ----------------
    const int am = t >> 2, akq = t & 3;        // A: row(0..63), chunk (2 of 8)
    const int wn = t & 31, kw = t >> 5;        // W: n-row(0..31), word (0..7)
    const __half* aptr = g_xh + (size_t)am * KDIM + akq * 8;   // chunks akq, akq+4
    const int*    bptr = gB + (size_t)kw * NDIM + n0 + wn;
    const float*  sptr = gs + n0 + wn;
    const uint32_t sAoff = (uint32_t)(am * ASTRIDE + akq * 16);
    const uint32_t sWoff = (uint32_t)(wn * ASTRIDE + kw * 16);

    uint32_t rw[4];          // B prefetch: 4 iteration slots
    float    rsv[4];

    auto ldgB = [&](int it) {
        const int sl = it & 3;
        rw[sl] = bptr[(size_t)it * 8 * NDIM];
        rsv[sl] = sptr[(size_t)(it >> 1) * NDIM];
    };
    auto stsW = [&](int it) {
        const int sl = it & 3;
        const __half2 s2 = __half2half2(__float2half_rn(rsv[sl]));
        unsigned char* wt = dsm + (it & (NST - 1)) * STG_BYTES + A_STG;
        *(uint4*)(wt + sWoff) = dq8(rw[sl], s2);
    };
    auto cpA = [&](int it) {
        const uint32_t dst = sb0 + (it & (NST - 1)) * STG_BYTES + sAoff;
        const __half* src = aptr + it * KTILE;
        CP_ASYNC16(dst, src);
        CP_ASYNC16(dst + 64, src + 32);
    };

    // ---------------- compute-phase mapping ----------------
    // 2 output tiles of 32x32 (m halves), 4 warps per tile split by k16 step.
    const int tile = wid >> 2;                 // 0,1 -> m 0..31 / 32..63
    const int kq   = wid & 3;                  // k16 step within KTILE=64
    const int tm = tile * 32;
    const int mat = lane >> 3, mr = lane & 7;
    const uint32_t aRow = (uint32_t)((tm + (mat & 1) * 8 + mr) * ASTRIDE
                                     + (mat >> 1) * 16 + kq * 32);
    const uint32_t bRow = (uint32_t)(((mat >> 1) * 8 + mr) * ASTRIDE
                                     + (mat & 1) * 16 + kq * 32);

    float acc[2][4][4];
    #pragma unroll
    for (int i = 0; i < 2; ++i)
        #pragma unroll
        for (int j = 0; j < 4; ++j)
            #pragma unroll
            for (int r = 0; r < 4; ++r) acc[i][j][r] = 0.f;

    auto compute = [&](int stg) {
        const uint32_t sAs = sb0 + stg * STG_BYTES;
        const uint32_t sWs = sAs + A_STG;
        uint32_t a0[4], a1[4], b0[4], b1[4];
        LDSM4(a0, sAs + aRow);
        LDSM4(a1, sAs + aRow + 16 * ASTRIDE);
        LDSM4(b0, sWs + bRow);
        LDSM4(b1, sWs + bRow + 16 * ASTRIDE);
        MMA16816(acc[0][0], a0, b0[0], b0[1]);
        MMA16816(acc[0][1], a0, b0[2], b0[3]);
        MMA16816(acc[0][2], a0, b1[0], b1[1]);
        MMA16816(acc[0][3], a0, b1[2], b1[3]);
        MMA16816(acc[1][0], a1, b0[0], b0[1]);
        MMA16816(acc[1][1], a1, b0[2], b0[3]);
        MMA16816(acc[1][2], a1, b1[0], b1[1]);
        MMA16816(acc[1][3], a1, b1[2], b1[3]);
    };

    // ---------------- prologue ----------------
    {   // iter 0 W: load directly and store to stage 0
        const __half2 s2 = __half2half2(__float2half_rn(sptr[0]));
        *(uint4*)(dsm + A_STG + sWoff) = dq8(bptr[0], s2);
    }
    ldgB(1);
    ldgB(2);
    cpA(0); CP_COMMIT();
    cpA(1); CP_COMMIT();

    // ---------------- main pipeline ----------------
    #pragma unroll 4
    for (int i = 0; i < NIT; ++i) {
        if (i + 1 < NIT) stsW(i + 1);      // dequant+store W for next iter
        if (i + 3 < NIT) ldgB(i + 3);      // B prefetch, 3 ahead
        if (i + 2 < NIT) cpA(i + 2);       // A prefetch, 2 ahead
        CP_COMMIT();
        CP_WAIT2();                        // A stage i arrived (this thread)
        __syncthreads();                   // stage i visible to all
        compute(i & (NST - 1));
    }
    __syncthreads();                       // protect smem reuse below

    // ---------------- 4-way k-split reduction + writeout ----------------
    // partials: 2 tiles x 3 writers x 1024 floats = 24 KB in dsm
    float* red = (float*)dsm;
    if (kq != 0) {
        float* dst = red + (tile * 3 + (kq - 1)) * 1024 + lane * 4;
        #pragma unroll
        for (int ms = 0; ms < 2; ++ms)
            #pragma unroll
            for (int ns = 0; ns < 4; ++ns) {
                float4 v = make_float4(acc[ms][ns][0], acc[ms][ns][1],
                                       acc[ms][ns][2], acc[ms][ns][3]);
                *(float4*)(dst + (ms * 4 + ns) * 128) = v;
            }
    }
    __syncthreads();
    if (kq == 0) {
        const float* src = red + tile * 3 * 1024 + lane * 4;
        const int g = lane >> 2, cb = 2 * (lane & 3);
        #pragma unroll
        for (int ms = 0; ms < 2; ++ms)
            #pragma unroll
            for (int ns = 0; ns < 4; ++ns) {
                const int off = (ms * 4 + ns) * 128;
                float4 v0 = *(const float4*)(src + off);
                float4 v1 = *(const float4*)(src + 1024 + off);
                float4 v2 = *(const float4*)(src + 2048 + off);
                const int m = tm + ms * 16 + g;
                const int c = n0 + ns * 8 + cb;
                float2 lo = make_float2(acc[ms][ns][0] + v0.x + v1.x + v2.x,
                                        acc[ms][ns][1] + v0.y + v1.y + v2.y);
                float2 hi = make_float2(acc[ms][ns][2] + v0.z + v1.z + v2.z,
                                        acc[ms][ns][3] + v0.w + v1.w + v2.w);
                *(float2*)(out + (size_t)m * NDIM + c)       = lo;
                *(float2*)(out + (size_t)(m + 8) * NDIM + c) = hi;
            }
    }
}

// ------------------------------- launch -------------------------------------
extern "C" void kernel_launch(void* const* d_in, const int* in_sizes, int n_in,
                              void* d_out, int out_size) {
    const float* x = (const float*)d_in[0];
    const int* B   = (const int*)d_in[1];
    const float* s = (const float*)d_in[2];
    float* out = (float*)d_out;

    cudaFuncSetAttribute(machete_kernel,
                         cudaFuncAttributeMaxDynamicSharedMemorySize, SMEM_TOTAL);

    prep_kernel<<<(MDIM * KDIM + 255) / 256, 256>>>(x);
    machete_kernel<<<NDIM / NTILE, 256, SMEM_TOTAL>>>(B, s, out);
}